// round 2
// baseline (speedup 1.0000x reference)
#include <cuda_runtime.h>

// SpatialTransformer: vol [B=2, 192,192,192, C=1] fp32, affine [B,3,4] fp32.
// loc = A @ (mesh - center) + t + center; trilinear sample with clamp-to-edge
// matching the JAX reference's clip(floor) semantics exactly.

#define DIM 192
#define BATCH 2

__global__ __launch_bounds__(DIM) void st_warp_kernel(
    const float* __restrict__ vol,
    const float* __restrict__ aff,
    float* __restrict__ out)
{
    const int w = threadIdx.x;       // fastest dim
    const int h = blockIdx.x;
    const int d = blockIdx.y;
    const int b = blockIdx.z;

    const float ctr  = (DIM - 1) * 0.5f;   // 95.5
    const float maxl = (float)(DIM - 1);   // 191

    const float* A = aff + b * 12;
    // Uniform loads (same for whole block) — L1/const cached.
    const float a00 = A[0], a01 = A[1],  a02 = A[2],  a03 = A[3];
    const float a10 = A[4], a11 = A[5],  a12 = A[6],  a13 = A[7];
    const float a20 = A[8], a21 = A[9],  a22 = A[10], a23 = A[11];

    const float cd = (float)d - ctr;
    const float ch = (float)h - ctr;
    const float cw = (float)w - ctr;

    // loc = A @ centered + t + center   (coordinate order: [d, h, w])
    const float ld = fmaf(a00, cd, fmaf(a01, ch, fmaf(a02, cw, a03))) + ctr;
    const float lh = fmaf(a10, cd, fmaf(a11, ch, fmaf(a12, cw, a13))) + ctr;
    const float lw = fmaf(a20, cd, fmaf(a21, ch, fmaf(a22, cw, a23))) + ctr;

    // Per-dim interp setup, exactly mirroring the reference:
    //   cl = clip(l); l0 = clip(floor(l)); l1 = clip(l0+1);
    //   w0 = l1 - cl (floor-corner weight); w1 = 1 - w0 (ceil-corner weight)
    float cld = fminf(fmaxf(ld, 0.f), maxl);
    float f0d = fminf(fmaxf(floorf(ld), 0.f), maxl);
    float f1d = fminf(f0d + 1.f, maxl);
    float w0d = f1d - cld, w1d = 1.f - w0d;
    int   i0d = (int)f0d,  i1d = (int)f1d;

    float clh = fminf(fmaxf(lh, 0.f), maxl);
    float f0h = fminf(fmaxf(floorf(lh), 0.f), maxl);
    float f1h = fminf(f0h + 1.f, maxl);
    float w0h = f1h - clh, w1h = 1.f - w0h;
    int   i0h = (int)f0h,  i1h = (int)f1h;

    float clw = fminf(fmaxf(lw, 0.f), maxl);
    float f0w = fminf(fmaxf(floorf(lw), 0.f), maxl);
    float f1w = fminf(f0w + 1.f, maxl);
    float w0w = f1w - clw, w1w = 1.f - w0w;
    int   i0w = (int)f0w,  i1w = (int)f1w;

    const float* vb = vol + (size_t)b * (DIM * DIM * DIM);
    const int r00 = i0d * (DIM * DIM) + i0h * DIM;
    const int r01 = i0d * (DIM * DIM) + i1h * DIM;
    const int r10 = i1d * (DIM * DIM) + i0h * DIM;
    const int r11 = i1d * (DIM * DIM) + i1h * DIM;

    // 8 gathers (issue all loads up front for MLP)
    const float v000 = __ldg(vb + r00 + i0w);
    const float v001 = __ldg(vb + r00 + i1w);
    const float v010 = __ldg(vb + r01 + i0w);
    const float v011 = __ldg(vb + r01 + i1w);
    const float v100 = __ldg(vb + r10 + i0w);
    const float v101 = __ldg(vb + r10 + i1w);
    const float v110 = __ldg(vb + r11 + i0w);
    const float v111 = __ldg(vb + r11 + i1w);

    const float p00 = fmaf(v000, w0w, v001 * w1w);
    const float p01 = fmaf(v010, w0w, v011 * w1w);
    const float p10 = fmaf(v100, w0w, v101 * w1w);
    const float p11 = fmaf(v110, w0w, v111 * w1w);

    const float q0 = fmaf(p00, w0h, p01 * w1h);
    const float q1 = fmaf(p10, w0h, p11 * w1h);

    const float res = fmaf(q0, w0d, q1 * w1d);

    out[((size_t)b * DIM + d) * (DIM * DIM) + h * DIM + w] = res;
}

extern "C" void kernel_launch(void* const* d_in, const int* in_sizes, int n_in,
                              void* d_out, int out_size)
{
    const float* vol = (const float*)d_in[0];
    const float* aff = (const float*)d_in[1];
    float* out = (float*)d_out;

    dim3 grid(DIM, DIM, BATCH);
    dim3 block(DIM);
    st_warp_kernel<<<grid, block>>>(vol, aff, out);
}

// round 5
// speedup vs baseline: 1.3716x; 1.3716x over previous
#include <cuda_runtime.h>

// SpatialTransformer: vol [B=2, 192,192,192, 1] fp32, affine [B,3,4] fp32.
// Instruction-minimized version: lerp formulation, step-select addressing,
// 4 voxels/thread along w with STG.128, affine in __constant__.

#define DIM 192
#define BATCH 2
#define SLAB (DIM * DIM)   // 36864
#define ROWS DIM           // 192

__constant__ float c_aff[BATCH * 12];

__global__ __launch_bounds__(192) void st_warp_k4(
    const float* __restrict__ vol,
    float* __restrict__ out)
{
    const int tx = threadIdx.x;                    // 0..47 : w-group
    const int h  = blockIdx.x * 4 + threadIdx.y;   // blockDim.y = 4
    const int d  = blockIdx.y;
    const int b  = blockIdx.z;
    const int w0 = tx * 4;

    const float ctr  = (DIM - 1) * 0.5f;   // 95.5
    const float maxl = (float)(DIM - 1);   // 191

    const float* A = c_aff + b * 12;
    const float a00 = A[0], a01 = A[1],  a02 = A[2],  a03 = A[3];
    const float a10 = A[4], a11 = A[5],  a12 = A[6],  a13 = A[7];
    const float a20 = A[8], a21 = A[9],  a22 = A[10], a23 = A[11];

    const float cd = (float)d  - ctr;
    const float ch = (float)h  - ctr;
    const float cw = (float)w0 - ctr;

    // Sample location at k=0 (coordinate order [d,h,w]); along w it advances
    // by (a02, a12, a22) per voxel.
    const float ld0 = fmaf(a00, cd, fmaf(a01, ch, fmaf(a02, cw, a03))) + ctr;
    const float lh0 = fmaf(a10, cd, fmaf(a11, ch, fmaf(a12, cw, a13))) + ctr;
    const float lw0 = fmaf(a20, cd, fmaf(a21, ch, fmaf(a22, cw, a23))) + ctr;

    const float* vb = vol + (size_t)b * (DIM * DIM * DIM);

    float r[4];

#pragma unroll
    for (int k = 0; k < 4; k++) {
        const float fk = (float)k;
        const float ldv = fmaf(a02, fk, ld0);
        const float lhv = fmaf(a12, fk, lh0);
        const float lwv = fmaf(a22, fk, lw0);

        // Per-dim: clamp, floor-as-trunc, frac weight, edge step-select.
        // Matches reference clip(floor)/clip(l0+1) semantics: at the upper
        // edge i1==i0 so v1-v0==0 and t is irrelevant; at the lower edge
        // cl=0 -> t=0 -> picks v0.
        const float sd = fminf(fmaxf(ldv, 0.f), maxl);
        const int   id = (int)sd;
        const float td = sd - (float)id;
        const int   od = (id < DIM - 1) ? SLAB : 0;

        const float sh = fminf(fmaxf(lhv, 0.f), maxl);
        const int   ih = (int)sh;
        const float th = sh - (float)ih;
        const int   oh = (ih < DIM - 1) ? ROWS : 0;

        const float sw = fminf(fmaxf(lwv, 0.f), maxl);
        const int   iw = (int)sw;
        const float tw = sw - (float)iw;
        const int   ow = (iw < DIM - 1) ? 1 : 0;

        const int base = id * SLAB + ih * ROWS + iw;
        const float* p = vb + base;

        const float v000 = __ldg(p);
        const float v001 = __ldg(p + ow);
        const float v010 = __ldg(p + oh);
        const float v011 = __ldg(p + oh + ow);
        const float v100 = __ldg(p + od);
        const float v101 = __ldg(p + od + ow);
        const float v110 = __ldg(p + od + oh);
        const float v111 = __ldg(p + od + oh + ow);

        const float p00 = fmaf(tw, v001 - v000, v000);
        const float p01 = fmaf(tw, v011 - v010, v010);
        const float p10 = fmaf(tw, v101 - v100, v100);
        const float p11 = fmaf(tw, v111 - v110, v110);

        const float q0 = fmaf(th, p01 - p00, p00);
        const float q1 = fmaf(th, p11 - p10, p10);

        r[k] = fmaf(td, q1 - q0, q0);
    }

    float4* o = (float4*)(out + ((size_t)(b * DIM + d) * DIM + h) * DIM + w0);
    *o = make_float4(r[0], r[1], r[2], r[3]);
}

extern "C" void kernel_launch(void* const* d_in, const int* in_sizes, int n_in,
                              void* d_out, int out_size)
{
    const float* vol = (const float*)d_in[0];
    const float* aff = (const float*)d_in[1];
    float* out = (float*)d_out;

    // Affine (96 B) into constant memory: D2D async copy, graph-capturable.
    cudaMemcpyToSymbolAsync(c_aff, aff, BATCH * 12 * sizeof(float), 0,
                            cudaMemcpyDeviceToDevice, 0);

    dim3 grid(DIM / 4, DIM, BATCH);
    dim3 block(DIM / 4, 4);
    st_warp_k4<<<grid, block>>>(vol, out);
}